// round 14
// baseline (speedup 1.0000x reference)
#include <cuda_runtime.h>
#include <cuda_fp16.h>
#include <cstdint>
#include <math.h>

#define N_NODES 100000
#define N_EDGES 1600000
#define D 128
#define NLAYER 3
#define LN_EPS 1e-5f
#define NBLK 98  // (N_NODES + 1023) / 1024

// ---------------- scratch (static __device__; referenced ONLY in device code) ----------------
__device__ float g_h[N_NODES * D];        // residual stream (fp32 master; layer0 uses x)
__device__ float g_hsum[N_NODES * D];     // jumping-knowledge sum (fp32)
__device__ uint32_t g_hA[N_NODES * 64];   // fp16 mirror of h, buffer A (even layers read)
__device__ uint32_t g_hB[N_NODES * 64];   // fp16 mirror of h, buffer B (odd layers read)
__device__ int g_deg[N_NODES];            // zeroed by k_scan_addtop each call
__device__ int g_off[N_NODES + 1];
__device__ int g_cur[N_NODES];
__device__ int g_col[N_EDGES];
__device__ int g_bsum[128];
__device__ uint32_t g_bh[7 * 128 * 64];   // weights transposed [n][kpair], packed half2

// ================= helpers =================
__device__ __forceinline__ uint32_t packh2(float a, float b) {
    __half2 h = __floats2half2_rn(a, b);
    return *(uint32_t*)&h;
}
__device__ __forceinline__ float gelu_exact(float v) {
    return 0.5f * v * (1.0f + erff(v * 0.70710678118654752f));
}

// ================= smem layout =================
#define SAK 68
#define OFF_RED 67584                 // after the fp32 C tile (128 x 132 x 4)
#define SMEM_TC (OFF_RED + 3072)      // 70656 bytes -> 2 CTAs/SM
#define OFF_REDF 34816                // k_final: red arrays right after A tile
#define CSTRIDE 132

__device__ __forceinline__ void mma_f16(float c[4], uint32_t a0, uint32_t a1, uint32_t a2,
                                        uint32_t a3, uint32_t b0, uint32_t b1) {
    asm volatile(
        "mma.sync.aligned.m16n8k16.row.col.f32.f16.f16.f32 "
        "{%0,%1,%2,%3}, {%4,%5,%6,%7}, {%8,%9}, {%0,%1,%2,%3};"
        : "+f"(c[0]), "+f"(c[1]), "+f"(c[2]), "+f"(c[3])
        : "r"(a0), "r"(a1), "r"(a2), "r"(a3), "r"(b0), "r"(b1));
}

// run 8 k-steps of 128x128 MMA from smem A (SAK stride) + global B
__device__ __forceinline__ void mma_tile(const uint32_t* As, const uint32_t* Bg, int mw,
                                         int nw, int g, int tg, float c[4][4][4]) {
#pragma unroll
    for (int mt = 0; mt < 4; mt++)
#pragma unroll
        for (int nt = 0; nt < 4; nt++)
#pragma unroll
            for (int e = 0; e < 4; e++) c[mt][nt][e] = 0.f;
#pragma unroll
    for (int ks = 0; ks < 8; ks++) {
        int kw = ks * 8 + tg;
        uint32_t a[4][4];
#pragma unroll
        for (int mt = 0; mt < 4; mt++) {
            int r0 = (mw + mt * 16 + g) * SAK;
            a[mt][0] = As[r0 + kw];
            a[mt][1] = As[r0 + 8 * SAK + kw];
            a[mt][2] = As[r0 + kw + 4];
            a[mt][3] = As[r0 + 8 * SAK + kw + 4];
        }
        uint32_t b[4][2];
#pragma unroll
        for (int nt = 0; nt < 4; nt++) {
            int n0 = (nw + nt * 8 + g) << 6;
            b[nt][0] = __ldg(&Bg[n0 + kw]);
            b[nt][1] = __ldg(&Bg[n0 + kw + 4]);
        }
#pragma unroll
        for (int mt = 0; mt < 4; mt++)
#pragma unroll
            for (int nt = 0; nt < 4; nt++)
                mma_f16(c[mt][nt], a[mt][0], a[mt][1], a[mt][2], a[mt][3], b[nt][0], b[nt][1]);
    }
}

// ================= fused prologue: hA mirror from x, hist, convert weights =================
__global__ void k_pro(const float* __restrict__ x, const int* __restrict__ dst,
                      const float* __restrict__ W1, const float* __restrict__ W2,
                      const float* __restrict__ pW) {
    int i = blockIdx.x * blockDim.x + threadIdx.x;
    if (i < N_NODES * 64) g_hA[i] = packh2(x[2 * i], x[2 * i + 1]);
    if (i < N_EDGES) atomicAdd(&g_deg[__ldg(&dst[i])], 1);
    if (i < 7 * 128 * 64) {
        int mat = i >> 13;
        int rem = i & 8191;
        int n = rem >> 6;
        int kw = rem & 63;
        const float* Bw = (mat < 3) ? (W1 + (size_t)mat * 16384)
                                    : ((mat < 6) ? (W2 + (size_t)(mat - 3) * 16384) : pW);
        float v0 = __ldg(&Bw[(size_t)(2 * kw) * 128 + n]);
        float v1 = __ldg(&Bw[(size_t)(2 * kw + 1) * 128 + n]);
        g_bh[i] = packh2(v0, v1);
    }
}

// ================= CSR build =================
__global__ void k_scan_local() {
    __shared__ int s[1024];
    int i = blockIdx.x * 1024 + threadIdx.x;
    int v = (i < N_NODES) ? g_deg[i] : 0;
    s[threadIdx.x] = v;
    __syncthreads();
#pragma unroll
    for (int off = 1; off < 1024; off <<= 1) {
        int t = (threadIdx.x >= off) ? s[threadIdx.x - off] : 0;
        __syncthreads();
        s[threadIdx.x] += t;
        __syncthreads();
    }
    if (i < N_NODES) g_off[i] = s[threadIdx.x] - v;
    if (threadIdx.x == 1023) g_bsum[blockIdx.x] = s[1023];
}

// adds top prefix, seeds g_cur, zeroes g_deg for the NEXT call, writes off[N]
__global__ void k_scan_addtop() {
    __shared__ int sp[NBLK + 1];
    __shared__ int sb[NBLK];
    if (threadIdx.x < NBLK) sb[threadIdx.x] = g_bsum[threadIdx.x];
    __syncthreads();
    if (threadIdx.x == 0) {
        int run = 0;
        for (int b = 0; b < NBLK; b++) {
            sp[b] = run;
            run += sb[b];
        }
    }
    __syncthreads();
    int i = blockIdx.x * blockDim.x + threadIdx.x;
    if (i < N_NODES) {
        int o = g_off[i] + sp[i >> 10];
        g_off[i] = o;
        g_cur[i] = o;
        g_deg[i] = 0;
    }
    if (i == 0) g_off[N_NODES] = N_EDGES;
}

__global__ void k_scatter(const int* __restrict__ src, const int* __restrict__ dst) {
    int e = blockIdx.x * blockDim.x + threadIdx.x;
    if (e < N_EDGES) {
        int d = dst[e];
        int p = atomicAdd(&g_cur[d], 1);
        g_col[p] = src[e];
    }
}

// ================= fused layer: gather + MLP + LN + GELU + residual =================
// Phase A: warp-per-node fp16 gather from the READ buffer (hA for even li, hB
// for odd) -> smem A tile. Epilogue writes the OTHER buffer — no intra-launch
// race (that race was the R12 bug).
__global__ void __launch_bounds__(256, 2)
k_layer(int li, const float* __restrict__ x, const float* __restrict__ eps,
        const float* __restrict__ b1, const float* __restrict__ b2,
        const float* __restrict__ lng, const float* __restrict__ lnb) {
    extern __shared__ char sm[];
    const int tid = threadIdx.x;
    const int wid = tid >> 5;
    const int lane = tid & 31;
    const int bm = blockIdx.x * 128;
    const bool first = (li == 0);
    const bool last = (li == NLAYER - 1);
    const uint2* hh2 = (li & 1) ? (const uint2*)g_hB : (const uint2*)g_hA;
    uint32_t* hhout = (li & 1) ? g_hA : g_hB;
    uint32_t* As = (uint32_t*)sm;

    // --- Phase A: gather into A tile ---
    {
        float e1 = 1.0f + __ldg(&eps[li]);
        const float4* self4 = first ? (const float4*)x : (const float4*)g_h;
        for (int it = 0; it < 16; it++) {
            int m = wid * 16 + it;
            int n = bm + m;
            float4 acc = make_float4(0.f, 0.f, 0.f, 0.f);
            if (n < N_NODES) {
                float4 s = __ldg(&self4[(size_t)n * 32 + lane]);
                acc.x = s.x * e1;
                acc.y = s.y * e1;
                acc.z = s.z * e1;
                acc.w = s.w * e1;
                int beg = g_off[n];
                int cnt = g_off[n + 1] - beg;
                for (int base = 0; base < cnt; base += 32) {
                    int mm = min(32, cnt - base);
                    int id = (lane < mm) ? g_col[beg + base + lane] : 0;
                    int j = 0;
                    for (; j + 8 <= mm; j += 8) {
                        uint2 t[8];
#pragma unroll
                        for (int q = 0; q < 8; q++) {
                            int nb = __shfl_sync(0xffffffffu, id, j + q);
                            t[q] = __ldg(&hh2[(size_t)nb * 32 + lane]);
                        }
#pragma unroll
                        for (int q = 0; q < 8; q++) {
                            float2 f0 = __half22float2(*reinterpret_cast<const __half2*>(&t[q].x));
                            float2 f1 = __half22float2(*reinterpret_cast<const __half2*>(&t[q].y));
                            acc.x += f0.x;
                            acc.y += f0.y;
                            acc.z += f1.x;
                            acc.w += f1.y;
                        }
                    }
                    for (; j < mm; j++) {
                        int nb = __shfl_sync(0xffffffffu, id, j);
                        uint2 t = __ldg(&hh2[(size_t)nb * 32 + lane]);
                        float2 f0 = __half22float2(*reinterpret_cast<const __half2*>(&t.x));
                        float2 f1 = __half22float2(*reinterpret_cast<const __half2*>(&t.y));
                        acc.x += f0.x;
                        acc.y += f0.y;
                        acc.z += f1.x;
                        acc.w += f1.y;
                    }
                }
            }
            *(uint2*)&As[m * SAK + 2 * lane] =
                make_uint2(packh2(acc.x, acc.y), packh2(acc.z, acc.w));
        }
    }
    __syncthreads();

    const int g = lane >> 2, tg = lane & 3;
    const int mw = (wid & 1) * 64;
    const int nw = (wid >> 1) * 32;
    float c[4][4][4];

    // --- GEMM1: z @ W1 ---
    mma_tile(As, g_bh + li * 8192, mw, nw, g, tg, c);
    __syncthreads();

    // --- relu(z1 + b1) -> As (fp16, in place) ---
#pragma unroll
    for (int nt = 0; nt < 4; nt++) {
        int col = nw + nt * 8 + tg * 2;
        float bz0 = __ldg(&b1[col]);
        float bz1 = __ldg(&b1[col + 1]);
        int wc = (col >> 1);
#pragma unroll
        for (int mt = 0; mt < 4; mt++) {
            int r0 = mw + mt * 16 + g;
            As[r0 * SAK + wc] =
                packh2(fmaxf(c[mt][nt][0] + bz0, 0.f), fmaxf(c[mt][nt][1] + bz1, 0.f));
            As[(r0 + 8) * SAK + wc] =
                packh2(fmaxf(c[mt][nt][2] + bz0, 0.f), fmaxf(c[mt][nt][3] + bz1, 0.f));
        }
    }
    __syncthreads();

    // --- GEMM2: z1 @ W2 ---
    mma_tile(As, g_bh + (3 + li) * 8192, mw, nw, g, tg, c);
    __syncthreads();

    // --- write fragments (+b2) to smem C tile ---
    float* Cs = (float*)sm;
#pragma unroll
    for (int nt = 0; nt < 4; nt++) {
        int col = nw + nt * 8 + tg * 2;
        float bz0 = __ldg(&b2[col]);
        float bz1 = __ldg(&b2[col + 1]);
#pragma unroll
        for (int mt = 0; mt < 4; mt++) {
            int r0 = mw + mt * 16 + g;
            Cs[r0 * CSTRIDE + col] = c[mt][nt][0] + bz0;
            Cs[r0 * CSTRIDE + col + 1] = c[mt][nt][1] + bz1;
            Cs[(r0 + 8) * CSTRIDE + col] = c[mt][nt][2] + bz0;
            Cs[(r0 + 8) * CSTRIDE + col + 1] = c[mt][nt][3] + bz1;
        }
    }
    __syncthreads();

    // --- LN stats ---
    float* red = (float*)(sm + OFF_RED);
    float* red2 = red + 256;
    float* rmean = red2 + 256;
    float* rrstd = rmean + 128;
    {
        int r = tid >> 1;
        int h0 = (tid & 1) * 64;
        float s = 0.f, s2 = 0.f;
#pragma unroll 8
        for (int cc = 0; cc < 64; cc++) {
            float v = Cs[r * CSTRIDE + h0 + cc];
            s += v;
            s2 += v * v;
        }
        red[r * 2 + (tid & 1)] = s;
        red2[r * 2 + (tid & 1)] = s2;
    }
    __syncthreads();
    if (tid < 128) {
        float S = red[tid * 2] + red[tid * 2 + 1];
        float S2 = red2[tid * 2] + red2[tid * 2 + 1];
        float mean = S * (1.0f / 128.0f);
        float var = S2 * (1.0f / 128.0f) - mean * mean;
        rmean[tid] = mean;
        rrstd[tid] = rsqrtf(var + LN_EPS);
    }
    __syncthreads();

    // --- LN + GELU + residual + mirrors (2 cols per thread) ---
    const float* hsrc = first ? x : g_h;
#pragma unroll 4
    for (int i = 0; i < 32; i++) {
        int e = i * 256 + tid;  // col-pair index, 8192 total
        int r = e >> 6;
        int cp = e & 63;
        int cc = cp * 2;
        int gm = bm + r;
        if (gm < N_NODES) {
            float mean = rmean[r], rs = rrstd[r];
            float v0 = (Cs[r * CSTRIDE + cc] - mean) * rs * __ldg(&lng[cc]) + __ldg(&lnb[cc]);
            float v1 =
                (Cs[r * CSTRIDE + cc + 1] - mean) * rs * __ldg(&lng[cc + 1]) + __ldg(&lnb[cc + 1]);
            float g0 = gelu_exact(v0);
            float g1 = gelu_exact(v1);
            size_t gi = (size_t)gm * 128 + cc;
            float2 ho = *(const float2*)(hsrc + gi);
            float hn0 = g0 + ho.x;
            float hn1 = g1 + ho.y;
            *(float2*)(g_h + gi) = make_float2(hn0, hn1);
            if (!last) hhout[(size_t)gm * 64 + cp] = packh2(hn0, hn1);
            if (first) {
                *(float2*)(g_hsum + gi) = make_float2(hn0, hn1);
            } else {
                float2 hs = *(float2*)(g_hsum + gi);
                hs.x += hn0;
                hs.y += hn1;
                *(float2*)(g_hsum + gi) = hs;
            }
        }
    }
}

// ================= fused final: row-LN(hsum) @ pW + pb -> out =================
__global__ void __launch_bounds__(256, 2)
k_final(const float* __restrict__ pg, const float* __restrict__ pbln,
        const float* __restrict__ pbias, float* __restrict__ out) {
    extern __shared__ char sm[];
    const int tid = threadIdx.x;
    const int wid = tid >> 5;
    const int lane = tid & 31;
    const int bm = blockIdx.x * 128;
    uint32_t* As = (uint32_t*)sm;
    float* red = (float*)(sm + OFF_REDF);
    float* red2 = red + 256;
    float* rmean = red2 + 256;
    float* rrstd = rmean + 128;

    {
        int r = tid >> 1;
        int h0 = (tid & 1) * 64;
        int gm = bm + r;
        float s = 0.f, s2 = 0.f;
        if (gm < N_NODES) {
#pragma unroll
            for (int cc = 0; cc < 64; cc += 4) {
                float4 v = *(const float4*)(g_hsum + (size_t)gm * 128 + h0 + cc);
                s += (v.x + v.y) + (v.z + v.w);
                s2 += (v.x * v.x + v.y * v.y) + (v.z * v.z + v.w * v.w);
            }
        }
        red[r * 2 + (tid & 1)] = s;
        red2[r * 2 + (tid & 1)] = s2;
    }
    __syncthreads();
    if (tid < 128) {
        float S = red[tid * 2] + red[tid * 2 + 1];
        float S2 = red2[tid * 2] + red2[tid * 2 + 1];
        float mean = S * (1.0f / 128.0f);
        float var = S2 * (1.0f / 128.0f) - mean * mean;
        rmean[tid] = mean;
        rrstd[tid] = rsqrtf(var + LN_EPS);
    }
    __syncthreads();

#pragma unroll
    for (int i = 0; i < 16; i++) {
        int idx = tid + i * 256;
        int m = idx >> 5;
        int u = idx & 31;
        int gm = bm + m;
        float4 v = make_float4(0.f, 0.f, 0.f, 0.f);
        if (gm < N_NODES) v = *(const float4*)(g_hsum + (size_t)gm * 128 + 4 * u);
        float mean = rmean[m], rs = rrstd[m];
        float4 g4 = __ldg(&((const float4*)pg)[u]);
        float4 b4 = __ldg(&((const float4*)pbln)[u]);
        float o0 = (v.x - mean) * rs * g4.x + b4.x;
        float o1 = (v.y - mean) * rs * g4.y + b4.y;
        float o2 = (v.z - mean) * rs * g4.z + b4.z;
        float o3 = (v.w - mean) * rs * g4.w + b4.w;
        *(uint2*)&As[m * SAK + 2 * u] = make_uint2(packh2(o0, o1), packh2(o2, o3));
    }
    __syncthreads();

    const int g = lane >> 2, tg = lane & 3;
    const int mw = (wid & 1) * 64;
    const int nw = (wid >> 1) * 32;
    float c[4][4][4];
    mma_tile(As, g_bh + 6 * 8192, mw, nw, g, tg, c);
    __syncthreads();

    float* Cs = (float*)sm;
#pragma unroll
    for (int nt = 0; nt < 4; nt++) {
        int col = nw + nt * 8 + tg * 2;
        float bz0 = __ldg(&pbias[col]);
        float bz1 = __ldg(&pbias[col + 1]);
#pragma unroll
        for (int mt = 0; mt < 4; mt++) {
            int r0 = mw + mt * 16 + g;
            Cs[r0 * CSTRIDE + col] = c[mt][nt][0] + bz0;
            Cs[r0 * CSTRIDE + col + 1] = c[mt][nt][1] + bz1;
            Cs[(r0 + 8) * CSTRIDE + col] = c[mt][nt][2] + bz0;
            Cs[(r0 + 8) * CSTRIDE + col + 1] = c[mt][nt][3] + bz1;
        }
    }
    __syncthreads();
#pragma unroll
    for (int i = 0; i < 16; i++) {
        int idx = tid + i * 256;
        int m = idx >> 5;
        int c4 = (idx & 31) << 2;
        int gm = bm + m;
        if (gm < N_NODES) {
            float4 o;
            o.x = Cs[m * CSTRIDE + c4];
            o.y = Cs[m * CSTRIDE + c4 + 1];
            o.z = Cs[m * CSTRIDE + c4 + 2];
            o.w = Cs[m * CSTRIDE + c4 + 3];
            *(float4*)(out + (size_t)gm * 128 + c4) = o;
        }
    }
}

// ================= launch =================
extern "C" void kernel_launch(void* const* d_in, const int* in_sizes, int n_in,
                              void* d_out, int out_size) {
    const float* x = (const float*)d_in[0];
    const int* edge_index = (const int*)d_in[1];
    const float* W1 = (const float*)d_in[2];
    const float* b1 = (const float*)d_in[3];
    const float* W2 = (const float*)d_in[4];
    const float* b2 = (const float*)d_in[5];
    const float* eps = (const float*)d_in[6];
    const float* ln_g = (const float*)d_in[7];
    const float* ln_b = (const float*)d_in[8];
    const float* pln_g = (const float*)d_in[9];
    const float* pln_b = (const float*)d_in[10];
    const float* pW = (const float*)d_in[11];
    const float* pb = (const float*)d_in[12];
    float* out = (float*)d_out;

    const int* src = edge_index;
    const int* dst = edge_index + N_EDGES;

    cudaFuncSetAttribute(k_layer, cudaFuncAttributeMaxDynamicSharedMemorySize, SMEM_TC);
    cudaFuncSetAttribute(k_final, cudaFuncAttributeMaxDynamicSharedMemorySize, SMEM_TC);

    // prologue + CSR build
    k_pro<<<(N_NODES * 64 + 255) / 256, 256>>>(x, dst, W1, W2, pW);
    k_scan_local<<<NBLK, 1024>>>();
    k_scan_addtop<<<(N_NODES + 255) / 256, 256>>>();
    k_scatter<<<(N_EDGES + 255) / 256, 256>>>(src, dst);

    int gblocks = (N_NODES + 127) / 128;  // 782
    for (int i = 0; i < NLAYER; i++) {
        k_layer<<<gblocks, 256, SMEM_TC>>>(i, x, eps, b1 + (size_t)i * D, b2 + (size_t)i * D,
                                           ln_g + (size_t)i * D, ln_b + (size_t)i * D);
    }
    k_final<<<gblocks, 256, SMEM_TC>>>(pln_g, pln_b, pb, out);
}

// round 16
// speedup vs baseline: 1.1153x; 1.1153x over previous
#include <cuda_runtime.h>
#include <cuda_fp16.h>
#include <cstdint>
#include <math.h>

#define N_NODES 100000
#define N_EDGES 1600000
#define D 128
#define NLAYER 3
#define LN_EPS 1e-5f
#define NBLK 98  // (N_NODES + 1023) / 1024

// ---------------- scratch (static __device__; referenced ONLY in device code) ----------------
__device__ float g_h[N_NODES * D];        // residual stream (fp32 master; layer0 uses x)
__device__ float g_hsum[N_NODES * D];     // jumping-knowledge sum (fp32; last layer keeps in smem)
__device__ uint32_t g_hh[N_NODES * 64];   // fp16 mirror of h (gather input)
__device__ uint32_t g_zh[N_NODES * 64];   // z as packed half2 (GEMM A input)
__device__ int g_deg[N_NODES];            // zeroed by k_scan_addtop each call
__device__ int g_off[N_NODES + 1];
__device__ int g_cur[N_NODES];
__device__ int g_col[N_EDGES];
__device__ int g_bsum[128];
__device__ uint32_t g_bh[7 * 128 * 64];   // weights transposed [n][kpair], packed half2

// ================= helpers =================
__device__ __forceinline__ uint32_t packh2(float a, float b) {
    __half2 h = __floats2half2_rn(a, b);
    return *(uint32_t*)&h;
}
__device__ __forceinline__ float gelu_exact(float v) {
    return 0.5f * v * (1.0f + erff(v * 0.70710678118654752f));
}

// ================= smem layout =================
// [0, 34816)        : A tile (fp16, SAK=68 words/row)  -- GEMM1/GEMM2 input
// [0, 67584)        : C tile (fp32, CSTRIDE=132)       -- overwrites A after GEMM2
// [67584, 70656)    : red arrays (LN stats)
// [70656, 105472)   : A2 tile (fp16)                   -- last layer's final GEMM input
#define SAK 68
#define OFF_RED 67584
#define OFF_A2 70656
#define SMEM_TC (OFF_A2 + 34816)      // 105472 bytes -> 2 CTAs/SM (211KB < 227KB)
#define CSTRIDE 132

__device__ __forceinline__ void mma_f16(float c[4], uint32_t a0, uint32_t a1, uint32_t a2,
                                        uint32_t a3, uint32_t b0, uint32_t b1) {
    asm volatile(
        "mma.sync.aligned.m16n8k16.row.col.f32.f16.f16.f32 "
        "{%0,%1,%2,%3}, {%4,%5,%6,%7}, {%8,%9}, {%0,%1,%2,%3};"
        : "+f"(c[0]), "+f"(c[1]), "+f"(c[2]), "+f"(c[3])
        : "r"(a0), "r"(a1), "r"(a2), "r"(a3), "r"(b0), "r"(b1));
}

// run 8 k-steps of 128x128 MMA from smem A (SAK stride) + global B
__device__ __forceinline__ void mma_tile(const uint32_t* As, const uint32_t* Bg, int mw,
                                         int nw, int g, int tg, float c[4][4][4]) {
#pragma unroll
    for (int mt = 0; mt < 4; mt++)
#pragma unroll
        for (int nt = 0; nt < 4; nt++)
#pragma unroll
            for (int e = 0; e < 4; e++) c[mt][nt][e] = 0.f;
#pragma unroll
    for (int ks = 0; ks < 8; ks++) {
        int kw = ks * 8 + tg;
        uint32_t a[4][4];
#pragma unroll
        for (int mt = 0; mt < 4; mt++) {
            int r0 = (mw + mt * 16 + g) * SAK;
            a[mt][0] = As[r0 + kw];
            a[mt][1] = As[r0 + 8 * SAK + kw];
            a[mt][2] = As[r0 + kw + 4];
            a[mt][3] = As[r0 + 8 * SAK + kw + 4];
        }
        uint32_t b[4][2];
#pragma unroll
        for (int nt = 0; nt < 4; nt++) {
            int n0 = (nw + nt * 8 + g) << 6;
            b[nt][0] = __ldg(&Bg[n0 + kw]);
            b[nt][1] = __ldg(&Bg[n0 + kw + 4]);
        }
#pragma unroll
        for (int mt = 0; mt < 4; mt++)
#pragma unroll
            for (int nt = 0; nt < 4; nt++)
                mma_f16(c[mt][nt], a[mt][0], a[mt][1], a[mt][2], a[mt][3], b[nt][0], b[nt][1]);
    }
}

// LN stats over the fp32 C tile: 2 threads per row, 64 cols each
__device__ __forceinline__ void ln_stats(const float* Cs, float* red, float* red2,
                                         float* rmean, float* rrstd, int tid) {
    {
        int r = tid >> 1;
        int h0 = (tid & 1) * 64;
        float s = 0.f, s2 = 0.f;
#pragma unroll 8
        for (int cc = 0; cc < 64; cc++) {
            float v = Cs[r * CSTRIDE + h0 + cc];
            s += v;
            s2 += v * v;
        }
        red[r * 2 + (tid & 1)] = s;
        red2[r * 2 + (tid & 1)] = s2;
    }
    __syncthreads();
    if (tid < 128) {
        float S = red[tid * 2] + red[tid * 2 + 1];
        float S2 = red2[tid * 2] + red2[tid * 2 + 1];
        float mean = S * (1.0f / 128.0f);
        float var = S2 * (1.0f / 128.0f) - mean * mean;
        rmean[tid] = mean;
        rrstd[tid] = rsqrtf(var + LN_EPS);
    }
    __syncthreads();
}

// ================= fused prologue: hh mirror from x, hist, convert weights =================
__global__ void k_pro(const float* __restrict__ x, const int* __restrict__ dst,
                      const float* __restrict__ W1, const float* __restrict__ W2,
                      const float* __restrict__ pW) {
    int i = blockIdx.x * blockDim.x + threadIdx.x;
    if (i < N_NODES * 64) g_hh[i] = packh2(x[2 * i], x[2 * i + 1]);
    if (i < N_EDGES) atomicAdd(&g_deg[__ldg(&dst[i])], 1);
    if (i < 7 * 128 * 64) {
        int mat = i >> 13;
        int rem = i & 8191;
        int n = rem >> 6;
        int kw = rem & 63;
        const float* Bw = (mat < 3) ? (W1 + (size_t)mat * 16384)
                                    : ((mat < 6) ? (W2 + (size_t)(mat - 3) * 16384) : pW);
        float v0 = __ldg(&Bw[(size_t)(2 * kw) * 128 + n]);
        float v1 = __ldg(&Bw[(size_t)(2 * kw + 1) * 128 + n]);
        g_bh[i] = packh2(v0, v1);
    }
}

// ================= CSR build =================
__global__ void k_scan_local() {
    __shared__ int s[1024];
    int i = blockIdx.x * 1024 + threadIdx.x;
    int v = (i < N_NODES) ? g_deg[i] : 0;
    s[threadIdx.x] = v;
    __syncthreads();
#pragma unroll
    for (int off = 1; off < 1024; off <<= 1) {
        int t = (threadIdx.x >= off) ? s[threadIdx.x - off] : 0;
        __syncthreads();
        s[threadIdx.x] += t;
        __syncthreads();
    }
    if (i < N_NODES) g_off[i] = s[threadIdx.x] - v;
    if (threadIdx.x == 1023) g_bsum[blockIdx.x] = s[1023];
}

// adds top prefix, seeds g_cur, zeroes g_deg for the NEXT call, writes off[N]
__global__ void k_scan_addtop() {
    __shared__ int sp[NBLK + 1];
    __shared__ int sb[NBLK];
    if (threadIdx.x < NBLK) sb[threadIdx.x] = g_bsum[threadIdx.x];
    __syncthreads();
    if (threadIdx.x == 0) {
        int run = 0;
        for (int b = 0; b < NBLK; b++) {
            sp[b] = run;
            run += sb[b];
        }
    }
    __syncthreads();
    int i = blockIdx.x * blockDim.x + threadIdx.x;
    if (i < N_NODES) {
        int o = g_off[i] + sp[i >> 10];
        g_off[i] = o;
        g_cur[i] = o;
        g_deg[i] = 0;
    }
    if (i == 0) g_off[N_NODES] = N_EDGES;
}

__global__ void k_scatter(const int* __restrict__ src, const int* __restrict__ dst) {
    int e = blockIdx.x * blockDim.x + threadIdx.x;
    if (e < N_EDGES) {
        int d = dst[e];
        int p = atomicAdd(&g_cur[d], 1);
        g_col[p] = src[e];
    }
}

// ================= aggregation: warp per node, fp16 gather, fp32 accumulate =================
__global__ __launch_bounds__(256) void k_agg(const float* __restrict__ x,
                                             const float* __restrict__ eps, int layer) {
    int wid = threadIdx.x >> 5, lane = threadIdx.x & 31;
    int n = blockIdx.x * 8 + wid;
    if (n >= N_NODES) return;
    float e1 = 1.0f + __ldg(&eps[layer]);
    const float4* self4 = (layer == 0) ? (const float4*)x : (const float4*)g_h;
    float4 self = __ldg(&self4[(size_t)n * 32 + lane]);
    float4 acc;
    acc.x = self.x * e1;
    acc.y = self.y * e1;
    acc.z = self.z * e1;
    acc.w = self.w * e1;
    int beg = g_off[n];
    int cnt = g_off[n + 1] - beg;
    const uint2* hh2 = (const uint2*)g_hh;
    for (int base = 0; base < cnt; base += 32) {
        int m = min(32, cnt - base);
        int id = (lane < m) ? g_col[beg + base + lane] : 0;
        int j = 0;
        for (; j + 16 <= m; j += 16) {
            uint2 t[16];
#pragma unroll
            for (int q = 0; q < 16; q++) {
                int nb = __shfl_sync(0xffffffffu, id, j + q);
                t[q] = __ldg(&hh2[(size_t)nb * 32 + lane]);
            }
#pragma unroll
            for (int q = 0; q < 16; q++) {
                float2 f0 = __half22float2(*reinterpret_cast<const __half2*>(&t[q].x));
                float2 f1 = __half22float2(*reinterpret_cast<const __half2*>(&t[q].y));
                acc.x += f0.x;
                acc.y += f0.y;
                acc.z += f1.x;
                acc.w += f1.y;
            }
        }
        for (; j + 4 <= m; j += 4) {
            uint2 t[4];
#pragma unroll
            for (int q = 0; q < 4; q++) {
                int nb = __shfl_sync(0xffffffffu, id, j + q);
                t[q] = __ldg(&hh2[(size_t)nb * 32 + lane]);
            }
#pragma unroll
            for (int q = 0; q < 4; q++) {
                float2 f0 = __half22float2(*reinterpret_cast<const __half2*>(&t[q].x));
                float2 f1 = __half22float2(*reinterpret_cast<const __half2*>(&t[q].y));
                acc.x += f0.x;
                acc.y += f0.y;
                acc.z += f1.x;
                acc.w += f1.y;
            }
        }
        for (; j < m; j++) {
            int nb = __shfl_sync(0xffffffffu, id, j);
            uint2 t = __ldg(&hh2[(size_t)nb * 32 + lane]);
            float2 f0 = __half22float2(*reinterpret_cast<const __half2*>(&t.x));
            float2 f1 = __half22float2(*reinterpret_cast<const __half2*>(&t.y));
            acc.x += f0.x;
            acc.y += f0.y;
            acc.z += f1.x;
            acc.w += f1.y;
        }
    }
    uint2 o = make_uint2(packh2(acc.x, acc.y), packh2(acc.z, acc.w));
    ((uint2*)g_zh)[(size_t)n * 32 + lane] = o;
}

// ================= fused per-layer MLP (+ final LN/GEMM on the last layer) =================
__global__ void __launch_bounds__(256, 2)
k_mlp(int li, const float* __restrict__ x, const float* __restrict__ b1,
      const float* __restrict__ b2, const float* __restrict__ lng,
      const float* __restrict__ lnb, const float* __restrict__ pg,
      const float* __restrict__ pbln, const float* __restrict__ pbias,
      float* __restrict__ out) {
    extern __shared__ char sm[];
    const int tid = threadIdx.x;
    const int wid = tid >> 5;
    const int lane = tid & 31;
    const int bm = blockIdx.x * 128;
    const bool first = (li == 0);
    const bool last = (li == NLAYER - 1);
    uint32_t* As = (uint32_t*)sm;

    // --- stage z tile (packed fp16 copy) ---
#pragma unroll
    for (int i = 0; i < 8; i++) {
        int idx = tid + i * 256;  // uint4 units, 2048 total
        int m = idx >> 4;
        int wq = (idx & 15) << 2;
        uint4 v = make_uint4(0u, 0u, 0u, 0u);
        int gm = bm + m;
        if (gm < N_NODES) v = __ldg(&((const uint4*)g_zh)[(size_t)gm * 16 + (wq >> 2)]);
        *(uint4*)&As[m * SAK + wq] = v;
    }
    __syncthreads();

    const int g = lane >> 2, tg = lane & 3;
    const int mw = (wid & 1) * 64;
    const int nw = (wid >> 1) * 32;
    float c[4][4][4];

    // --- GEMM1: z @ W1 ---
    mma_tile(As, g_bh + li * 8192, mw, nw, g, tg, c);
    __syncthreads();

    // --- relu(z1 + b1) -> As (fp16, in place) ---
#pragma unroll
    for (int nt = 0; nt < 4; nt++) {
        int col = nw + nt * 8 + tg * 2;
        float bz0 = __ldg(&b1[col]);
        float bz1 = __ldg(&b1[col + 1]);
        int wc = (col >> 1);
#pragma unroll
        for (int mt = 0; mt < 4; mt++) {
            int r0 = mw + mt * 16 + g;
            As[r0 * SAK + wc] =
                packh2(fmaxf(c[mt][nt][0] + bz0, 0.f), fmaxf(c[mt][nt][1] + bz1, 0.f));
            As[(r0 + 8) * SAK + wc] =
                packh2(fmaxf(c[mt][nt][2] + bz0, 0.f), fmaxf(c[mt][nt][3] + bz1, 0.f));
        }
    }
    __syncthreads();

    // --- GEMM2: z1 @ W2 ---
    mma_tile(As, g_bh + (3 + li) * 8192, mw, nw, g, tg, c);
    __syncthreads();

    // --- write fragments (+b2) to smem C tile ---
    float* Cs = (float*)sm;
#pragma unroll
    for (int nt = 0; nt < 4; nt++) {
        int col = nw + nt * 8 + tg * 2;
        float bz0 = __ldg(&b2[col]);
        float bz1 = __ldg(&b2[col + 1]);
#pragma unroll
        for (int mt = 0; mt < 4; mt++) {
            int r0 = mw + mt * 16 + g;
            Cs[r0 * CSTRIDE + col] = c[mt][nt][0] + bz0;
            Cs[r0 * CSTRIDE + col + 1] = c[mt][nt][1] + bz1;
            Cs[(r0 + 8) * CSTRIDE + col] = c[mt][nt][2] + bz0;
            Cs[(r0 + 8) * CSTRIDE + col + 1] = c[mt][nt][3] + bz1;
        }
    }
    __syncthreads();

    // --- LN stats over z2 ---
    float* red = (float*)(sm + OFF_RED);
    float* red2 = red + 256;
    float* rmean = red2 + 256;
    float* rrstd = rmean + 128;
    ln_stats(Cs, red, red2, rmean, rrstd, tid);

    // --- LN + GELU + residual (2 cols per thread) ---
    const float* hsrc = first ? x : g_h;
#pragma unroll 4
    for (int i = 0; i < 32; i++) {
        int e = i * 256 + tid;  // col-pair index, 8192 total
        int r = e >> 6;
        int cp = e & 63;
        int cc = cp * 2;
        int gm = bm + r;
        if (gm < N_NODES) {
            float mean = rmean[r], rs = rrstd[r];
            float v0 = (Cs[r * CSTRIDE + cc] - mean) * rs * __ldg(&lng[cc]) + __ldg(&lnb[cc]);
            float v1 =
                (Cs[r * CSTRIDE + cc + 1] - mean) * rs * __ldg(&lng[cc + 1]) + __ldg(&lnb[cc + 1]);
            float g0 = gelu_exact(v0);
            float g1 = gelu_exact(v1);
            size_t gi = (size_t)gm * 128 + cc;
            float2 ho = *(const float2*)(hsrc + gi);
            float hn0 = g0 + ho.x;
            float hn1 = g1 + ho.y;
            if (!last) {
                *(float2*)(g_h + gi) = make_float2(hn0, hn1);
                g_hh[(size_t)gm * 64 + cp] = packh2(hn0, hn1);
                if (first) {
                    *(float2*)(g_hsum + gi) = make_float2(hn0, hn1);
                } else {
                    float2 hs = *(float2*)(g_hsum + gi);
                    hs.x += hn0;
                    hs.y += hn1;
                    *(float2*)(g_hsum + gi) = hs;
                }
            } else {
                // last layer: hsum stays in smem (overwrite Cs in place)
                float2 hs = *(const float2*)(g_hsum + gi);
                Cs[r * CSTRIDE + cc] = hs.x + hn0;
                Cs[r * CSTRIDE + cc + 1] = hs.y + hn1;
            }
        } else if (last) {
            Cs[r * CSTRIDE + cc] = 0.f;
            Cs[r * CSTRIDE + cc + 1] = 0.f;
        }
    }

    if (!last) return;

    // ================= fused final: row-LN(hsum) @ pW + pb -> out =================
    __syncthreads();
    ln_stats(Cs, red, red2, rmean, rrstd, tid);

    // normalize + pack fp16 into the second A tile (doesn't alias Cs)
    uint32_t* A2 = (uint32_t*)(sm + OFF_A2);
#pragma unroll
    for (int i = 0; i < 16; i++) {
        int idx = tid + i * 256;
        int m = idx >> 5;
        int u = idx & 31;
        float mean = rmean[m], rs = rrstd[m];
        float4 g4 = __ldg(&((const float4*)pg)[u]);
        float4 b4 = __ldg(&((const float4*)pbln)[u]);
        float w0 = Cs[m * CSTRIDE + 4 * u];
        float w1 = Cs[m * CSTRIDE + 4 * u + 1];
        float w2 = Cs[m * CSTRIDE + 4 * u + 2];
        float w3 = Cs[m * CSTRIDE + 4 * u + 3];
        float o0 = (w0 - mean) * rs * g4.x + b4.x;
        float o1 = (w1 - mean) * rs * g4.y + b4.y;
        float o2 = (w2 - mean) * rs * g4.z + b4.z;
        float o3 = (w3 - mean) * rs * g4.w + b4.w;
        *(uint2*)&A2[m * SAK + 2 * u] = make_uint2(packh2(o0, o1), packh2(o2, o3));
    }
    __syncthreads();

    mma_tile(A2, g_bh + 6 * 8192, mw, nw, g, tg, c);
    __syncthreads();

#pragma unroll
    for (int nt = 0; nt < 4; nt++) {
        int col = nw + nt * 8 + tg * 2;
        float bz0 = __ldg(&pbias[col]);
        float bz1 = __ldg(&pbias[col + 1]);
#pragma unroll
        for (int mt = 0; mt < 4; mt++) {
            int r0 = mw + mt * 16 + g;
            Cs[r0 * CSTRIDE + col] = c[mt][nt][0] + bz0;
            Cs[r0 * CSTRIDE + col + 1] = c[mt][nt][1] + bz1;
            Cs[(r0 + 8) * CSTRIDE + col] = c[mt][nt][2] + bz0;
            Cs[(r0 + 8) * CSTRIDE + col + 1] = c[mt][nt][3] + bz1;
        }
    }
    __syncthreads();
#pragma unroll
    for (int i = 0; i < 16; i++) {
        int idx = tid + i * 256;
        int m = idx >> 5;
        int c4 = (idx & 31) << 2;
        int gm = bm + m;
        if (gm < N_NODES) {
            float4 o;
            o.x = Cs[m * CSTRIDE + c4];
            o.y = Cs[m * CSTRIDE + c4 + 1];
            o.z = Cs[m * CSTRIDE + c4 + 2];
            o.w = Cs[m * CSTRIDE + c4 + 3];
            *(float4*)(out + (size_t)gm * 128 + c4) = o;
        }
    }
}

// ================= launch =================
extern "C" void kernel_launch(void* const* d_in, const int* in_sizes, int n_in,
                              void* d_out, int out_size) {
    const float* x = (const float*)d_in[0];
    const int* edge_index = (const int*)d_in[1];
    const float* W1 = (const float*)d_in[2];
    const float* b1 = (const float*)d_in[3];
    const float* W2 = (const float*)d_in[4];
    const float* b2 = (const float*)d_in[5];
    const float* eps = (const float*)d_in[6];
    const float* ln_g = (const float*)d_in[7];
    const float* ln_b = (const float*)d_in[8];
    const float* pln_g = (const float*)d_in[9];
    const float* pln_b = (const float*)d_in[10];
    const float* pW = (const float*)d_in[11];
    const float* pb = (const float*)d_in[12];
    float* out = (float*)d_out;

    const int* src = edge_index;
    const int* dst = edge_index + N_EDGES;

    cudaFuncSetAttribute(k_mlp, cudaFuncAttributeMaxDynamicSharedMemorySize, SMEM_TC);

    // prologue + CSR build
    k_pro<<<(N_NODES * 64 + 255) / 256, 256>>>(x, dst, W1, W2, pW);
    k_scan_local<<<NBLK, 1024>>>();
    k_scan_addtop<<<(N_NODES + 255) / 256, 256>>>();
    k_scatter<<<(N_EDGES + 255) / 256, 256>>>(src, dst);

    int gblocks = (N_NODES + 127) / 128;  // 782
    int ablocks = (N_NODES + 7) / 8;      // 12500
    for (int i = 0; i < NLAYER; i++) {
        k_agg<<<ablocks, 256>>>(x, eps, i);
        k_mlp<<<gblocks, 256, SMEM_TC>>>(i, x, b1 + (size_t)i * D, b2 + (size_t)i * D,
                                         ln_g + (size_t)i * D, ln_b + (size_t)i * D,
                                         pln_g, pln_b, pb, out);
    }
}